// round 3
// baseline (speedup 1.0000x reference)
#include <cuda_runtime.h>
#include <math.h>

constexpr int D   = 128;
constexpr int NR  = 20;
constexpr int ET  = 64;    // edges per CTA
constexpr int NT  = 256;   // threads per CTA

// ---- device scratch (no allocations allowed) ----
__device__ float g_acc;                 // sum of r^2 (global Frobenius norm^2)
__device__ float g_W1T[D * D];          // W1T[d][f]
__device__ float g_W2T[D * 3 * D];      // W2T[k][ch], ch in [0,384)
__device__ float g_WwT[NR * 3 * D];     // WwT[n][ch]

// ---- smem layout (floats) ----
constexpr int OFF_A   = 0;                    // 64 x 132 (padded activations)
constexpr int OFF_W   = OFF_A  + ET * 132;    // 128 x 128 (current weight tile, transposed)
constexpr int OFF_S0  = OFF_W  + D * D;       // 64 x 128
constexpr int OFF_S2  = OFF_S0 + ET * D;      // 64 x 128
constexpr int OFF_FC  = OFF_S2 + ET * D;      // 64 x 20
constexpr int OFF_WW  = OFF_FC + ET * NR;     // 20 x 384
constexpr int OFF_ORG = OFF_WW + NR * 3 * D;  // 64 x 3
constexpr int OFF_B1  = OFF_ORG + ET * 3;     // 128
constexpr int OFF_B2  = OFF_B1 + D;           // 384
constexpr int OFF_BW  = OFF_B2 + 3 * D;       // 384
constexpr int OFF_IDX = OFF_BW + 3 * D;       // 64 ints
constexpr int SMEM_FLOATS = OFF_IDX + ET;
constexpr size_t SMEM_BYTES = (size_t)SMEM_FLOATS * 4;   // ~205 KB

// ============================================================
__global__ void zero_kernel(float* __restrict__ out, int n4) {
    int i = blockIdx.x * blockDim.x + threadIdx.x;
    if (i < n4) reinterpret_cast<float4*>(out)[i] = make_float4(0.f, 0.f, 0.f, 0.f);
    if (i == 0) g_acc = 0.f;
}

__global__ void norm_kernel(const float* __restrict__ r, int n) {
    __shared__ float red[NT];
    float s = 0.f;
    for (int i = blockIdx.x * blockDim.x + threadIdx.x; i < n; i += gridDim.x * blockDim.x) {
        float x = r[i];
        s += x * x;
    }
    red[threadIdx.x] = s;
    __syncthreads();
    for (int off = NT / 2; off > 0; off >>= 1) {
        if (threadIdx.x < off) red[threadIdx.x] += red[threadIdx.x + off];
        __syncthreads();
    }
    if (threadIdx.x == 0) atomicAdd(&g_acc, red[0]);
}

// generic transpose: src is R x C row-major; dst[c*R + r] = src[r*C + c]
// which: 0 -> g_W1T, 1 -> g_W2T, 2 -> g_WwT
__global__ void transpose_kernel(const float* __restrict__ src, int R, int C, int which) {
    __shared__ float tile[32][33];
    float* dst = (which == 0) ? g_W1T : (which == 1) ? g_W2T : g_WwT;
    int c0 = blockIdx.x * 32, r0 = blockIdx.y * 32;
    for (int j = threadIdx.y; j < 32; j += 8) {
        int y = r0 + j, x = c0 + threadIdx.x;
        if (y < R && x < C) tile[j][threadIdx.x] = src[y * C + x];
    }
    __syncthreads();
    for (int j = threadIdx.y; j < 32; j += 8) {
        int yc = c0 + j, xr = r0 + threadIdx.x;
        if (yc < C && xr < R) dst[yc * R + xr] = tile[threadIdx.x][j];
    }
}

// ============================================================
__device__ __forceinline__ void gemm_tile(const float* __restrict__ sA,
                                          const float* __restrict__ sW,
                                          int ty, int tx, float acc[4][8]) {
    const float* A0 = sA + (ty * 4 + 0) * 132;
    const float* A1 = A0 + 132;
    const float* A2 = A1 + 132;
    const float* A3 = A2 + 132;
    const float4* W4 = reinterpret_cast<const float4*>(sW);
#pragma unroll 4
    for (int k = 0; k < D; k++) {
        float4 b0 = W4[k * 32 + tx * 2];
        float4 b1 = W4[k * 32 + tx * 2 + 1];
        float a[4] = {A0[k], A1[k], A2[k], A3[k]};
#pragma unroll
        for (int i = 0; i < 4; i++) {
            acc[i][0] += a[i] * b0.x;  acc[i][1] += a[i] * b0.y;
            acc[i][2] += a[i] * b0.z;  acc[i][3] += a[i] * b0.w;
            acc[i][4] += a[i] * b1.x;  acc[i][5] += a[i] * b1.y;
            acc[i][6] += a[i] * b1.z;  acc[i][7] += a[i] * b1.w;
        }
    }
}

__device__ __forceinline__ void stage_w2(float* __restrict__ sW, int c, int tid) {
    const float4* src = reinterpret_cast<const float4*>(g_W2T);
    float4* dst = reinterpret_cast<float4*>(sW);
    for (int i = tid; i < D * 32; i += NT) {
        int k = i >> 5, fq = i & 31;
        dst[i] = src[k * 96 + c * 32 + fq];
    }
}

__global__ void __launch_bounds__(NT, 1) fused_kernel(
    const float* __restrict__ s, const float* __restrict__ r, const float* __restrict__ v,
    const float* __restrict__ b1, const float* __restrict__ b2, const float* __restrict__ bw,
    const int* __restrict__ idx_i,
    float* __restrict__ out_v, float* __restrict__ out_s, int E)
{
    extern __shared__ float sm[];
    float* sA  = sm + OFF_A;
    float* sW  = sm + OFF_W;
    int*   sIdx = reinterpret_cast<int*>(sm + OFF_IDX);

    const int tid = threadIdx.x;
    const int e0  = blockIdx.x * ET;
    const int tx  = tid & 15;        // output-feature tile: f0 = tx*8
    const int ty  = tid >> 4;        // edge tile: edges ty*4 .. ty*4+3
    const int f0  = tx * 8;

    // ---- stage s tile (pad rows to 132 floats) ----
    {
        const float4* src = reinterpret_cast<const float4*>(s) + (size_t)e0 * 32;
        for (int i = tid; i < ET * 32; i += NT) {
            int e = i >> 5, dq = i & 31;
            float4 val = (e0 + e < E) ? src[i] : make_float4(0.f, 0.f, 0.f, 0.f);
            *reinterpret_cast<float4*>(sA + e * 132 + dq * 4) = val;
        }
    }
    // ---- stage W1T (direct copy, conflict-free) ----
    {
        const float4* src = reinterpret_cast<const float4*>(g_W1T);
        float4* dst = reinterpret_cast<float4*>(sW);
        for (int i = tid; i < D * 32; i += NT) dst[i] = src[i];
    }
    // ---- stage WwT ----
    {
        const float4* src = reinterpret_cast<const float4*>(g_WwT);
        float4* dst = reinterpret_cast<float4*>(sm + OFF_WW);
        for (int i = tid; i < NR * 96; i += NT) dst[i] = src[i];
    }
    // ---- biases ----
    for (int i = tid; i < D; i += NT) sm[OFF_B1 + i] = b1[i];
    for (int i = tid; i < 3 * D; i += NT) { sm[OFF_B2 + i] = b2[i]; sm[OFF_BW + i] = bw[i]; }
    // ---- per-edge: idx, org (GLOBAL frobenius norm!), fcut features ----
    if (tid < ET) {
        int ge = e0 + tid;
        if (ge < E) {
            sIdx[tid] = idx_i[ge];
            float rx = r[ge * 3 + 0], ry = r[ge * 3 + 1], rz = r[ge * 3 + 2];
            float rn = sqrtf(rx * rx + ry * ry + rz * rz);
            float invg = rsqrtf(g_acc);   // reference: r / ||r||_F (whole array!)
            sm[OFF_ORG + tid * 3 + 0] = rx * invg;
            sm[OFF_ORG + tid * 3 + 1] = ry * invg;
            sm[OFF_ORG + tid * 3 + 2] = rz * invg;
            float inv_rn = 1.f / rn;
            float base = 0.62831853071795864f * rn;   // pi/RCUT * rn
#pragma unroll
            for (int n = 0; n < NR; n++) {
                float rbf = sinf((float)(n + 1) * base) * inv_rn;
                float fc = (rbf <= 5.0f) ? 0.5f * (cosf(0.62831853071795864f * rbf) + 1.0f) : 0.0f;
                sm[OFF_FC + tid * NR + n] = fc;
            }
        } else {
            sIdx[tid] = 0;
            sm[OFF_ORG + tid * 3 + 0] = 0.f; sm[OFF_ORG + tid * 3 + 1] = 0.f; sm[OFF_ORG + tid * 3 + 2] = 0.f;
#pragma unroll
            for (int n = 0; n < NR; n++) sm[OFF_FC + tid * NR + n] = 0.f;
        }
    }
    __syncthreads();

    // ================= GEMM1: h = silu(S @ W1^T + b1) =================
    float acc[4][8];
#pragma unroll
    for (int i = 0; i < 4; i++)
#pragma unroll
        for (int j = 0; j < 8; j++) acc[i][j] = 0.f;

    gemm_tile(sA, sW, ty, tx, acc);
    __syncthreads();   // all reads of sA / sW complete

    // silu -> write h back into sA (same padded layout); stage W2T chunk 0
#pragma unroll
    for (int i = 0; i < 4; i++) {
        int e = ty * 4 + i;
#pragma unroll
        for (int j = 0; j < 8; j++) {
            float x = acc[i][j] + sm[OFF_B1 + f0 + j];
            sA[e * 132 + f0 + j] = x / (1.f + __expf(-x));
        }
    }
    stage_w2(sW, 0, tid);
    __syncthreads();

    // ================= GEMM2 (3 chunks of 128 channels) + gate epilogue =================
    for (int c = 0; c < 3; c++) {
#pragma unroll
        for (int i = 0; i < 4; i++)
#pragma unroll
            for (int j = 0; j < 8; j++) acc[i][j] = 0.f;

        gemm_tile(sA, sW, ty, tx, acc);
        __syncthreads();   // reads of sW done
        if (c < 2) stage_w2(sW, c + 1, tid);

        const int chb = c * D + f0;
#pragma unroll
        for (int i = 0; i < 4; i++) {
            int e = ty * 4 + i;
            bool live = (e0 + e) < E;
            float wv[8];
#pragma unroll
            for (int j = 0; j < 8; j++) wv[j] = sm[OFF_BW + chb + j];
            const float* fcrow = sm + OFF_FC + e * NR;
#pragma unroll
            for (int n = 0; n < NR; n++) {
                float fc = fcrow[n];
                const float4* wwr = reinterpret_cast<const float4*>(sm + OFF_WW + n * 3 * D + chb);
                float4 w0 = wwr[0], w1 = wwr[1];
                wv[0] += fc * w0.x; wv[1] += fc * w0.y; wv[2] += fc * w0.z; wv[3] += fc * w0.w;
                wv[4] += fc * w1.x; wv[5] += fc * w1.y; wv[6] += fc * w1.z; wv[7] += fc * w1.w;
            }
            if (c == 0) {
#pragma unroll
                for (int j = 0; j < 8; j++)
                    sm[OFF_S0 + e * D + f0 + j] = wv[j] * (acc[i][j] + sm[OFF_B2 + chb + j]);
            } else if (c == 2) {
#pragma unroll
                for (int j = 0; j < 8; j++)
                    sm[OFF_S2 + e * D + f0 + j] = wv[j] * (acc[i][j] + sm[OFF_B2 + chb + j]);
            } else if (live) {
                float* dst = out_s + (size_t)sIdx[e] * D + f0;
#pragma unroll
                for (int j = 0; j < 8; j++)
                    atomicAdd(dst + j, wv[j] * (acc[i][j] + sm[OFF_B2 + chb + j]));
            }
        }
        __syncthreads();
    }

    // ================= vv = s2*org + s0*v ; scatter to out_v =================
    const float4* v4  = reinterpret_cast<const float4*>(v);
    const float4* S0q = reinterpret_cast<const float4*>(sm + OFF_S0);
    const float4* S2q = reinterpret_cast<const float4*>(sm + OFF_S2);
    for (int i = tid; i < ET * 96; i += NT) {
        int e = i / 96;
        if (e0 + e >= E) break;
        int rr = i - e * 96;
        int axis = rr >> 5, dq = rr & 31;
        float4 vval = v4[(size_t)(e0 + e) * 96 + rr];
        float4 s0v = S0q[e * 32 + dq];
        float4 s2v = S2q[e * 32 + dq];
        float o = sm[OFF_ORG + e * 3 + axis];
        float* dst = out_v + ((size_t)sIdx[e] * 3 + axis) * D + dq * 4;
        atomicAdd(dst + 0, s2v.x * o + s0v.x * vval.x);
        atomicAdd(dst + 1, s2v.y * o + s0v.y * vval.y);
        atomicAdd(dst + 2, s2v.z * o + s0v.z * vval.z);
        atomicAdd(dst + 3, s2v.w * o + s0v.w * vval.w);
    }
}

// ============================================================
extern "C" void kernel_launch(void* const* d_in, const int* in_sizes, int n_in,
                              void* d_out, int out_size) {
    const float* s   = (const float*)d_in[0];
    const float* r   = (const float*)d_in[1];
    const float* v   = (const float*)d_in[2];
    const float* W1  = (const float*)d_in[3];
    const float* b1  = (const float*)d_in[4];
    const float* W2  = (const float*)d_in[5];
    const float* b2  = (const float*)d_in[6];
    const float* Ww  = (const float*)d_in[7];
    const float* bw  = (const float*)d_in[8];
    const int*   idx = (const int*)d_in[9];
    const int E = in_sizes[9];
    const int N = out_size / (4 * D);            // out = N*3*D (out_v) + N*D (out_s)
    float* out_v = (float*)d_out;
    float* out_s = out_v + (size_t)N * 3 * D;

    cudaFuncSetAttribute(fused_kernel, cudaFuncAttributeMaxDynamicSharedMemorySize, (int)SMEM_BYTES);

    int n4 = out_size / 4;
    zero_kernel<<<(n4 + NT - 1) / NT, NT>>>((float*)d_out, n4);
    norm_kernel<<<256, NT>>>(r, E * 3);

    dim3 tb(32, 8);
    transpose_kernel<<<dim3(4, 4),  tb>>>(W1, D, D, 0);          // -> g_W1T [d][f]
    transpose_kernel<<<dim3(4, 12), tb>>>(W2, 3 * D, D, 1);      // -> g_W2T [k][ch]
    transpose_kernel<<<dim3(1, 12), tb>>>(Ww, 3 * D, NR, 2);     // -> g_WwT [n][ch]

    int grid = (E + ET - 1) / ET;
    fused_kernel<<<grid, NT, SMEM_BYTES>>>(s, r, v, b1, b2, bw, idx, out_v, out_s, E);
}

// round 4
// speedup vs baseline: 1.8681x; 1.8681x over previous
#include <cuda_runtime.h>
#include <math.h>

constexpr int D   = 128;
constexpr int NR  = 20;
constexpr int ET  = 128;   // edges per CTA
constexpr int NT  = 256;   // threads per CTA

// ---- device scratch (no allocations allowed) ----
__device__ float g_acc;                 // sum of r^2 (global Frobenius norm^2)
__device__ float g_W1T[D * D];          // W1T[k][f]
__device__ float g_W2T[D * 3 * D];      // W2T[k][ch], ch in [0,384)
__device__ float g_WwT[NR * 3 * D];     // WwT[n][ch]

// ---- smem layout (floats) ----
constexpr int OFF_A   = 0;                    // 128 x 132 (padded activations / h)
constexpr int OFF_W   = OFF_A  + ET * 132;    // 128 x 128 (current weight tile, [k][f])
constexpr int OFF_WW  = OFF_W  + D * D;       // 20 x 384
constexpr int OFF_FC  = OFF_WW + NR * 3 * D;  // 128 x 20
constexpr int OFF_ORG = OFF_FC + ET * NR;     // 128 x 3
constexpr int OFF_B1  = OFF_ORG + ET * 3;     // 128
constexpr int OFF_B2  = OFF_B1 + D;           // 384
constexpr int OFF_BW  = OFF_B2 + 3 * D;       // 384
constexpr int OFF_IDX = OFF_BW + 3 * D;       // 128 ints
constexpr int SMEM_FLOATS = OFF_IDX + ET;
constexpr size_t SMEM_BYTES = (size_t)SMEM_FLOATS * 4;   // ~176 KB

// ---- packed f32x2 helpers (Blackwell) ----
__device__ __forceinline__ void ffma2(unsigned long long& d, unsigned long long a, unsigned long long b) {
    asm("fma.rn.f32x2 %0, %1, %2, %0;" : "+l"(d) : "l"(a), "l"(b));
}
__device__ __forceinline__ unsigned long long dup2(float x) {
    unsigned long long r; asm("mov.b64 %0, {%1, %1};" : "=l"(r) : "f"(x)); return r;
}
__device__ __forceinline__ unsigned long long pack2(float x, float y) {
    unsigned long long r; asm("mov.b64 %0, {%1, %2};" : "=l"(r) : "f"(x), "f"(y)); return r;
}
__device__ __forceinline__ float2 unpack2(unsigned long long v) {
    float2 f; asm("mov.b64 {%0, %1}, %2;" : "=f"(f.x), "=f"(f.y) : "l"(v)); return f;
}
__device__ __forceinline__ void red2(float* p, float x, float y) {
    asm volatile("red.global.add.v2.f32 [%0], {%1, %2};" :: "l"(p), "f"(x), "f"(y) : "memory");
}

// ============================================================
__global__ void zero_kernel(float* __restrict__ out, int n4) {
    int i = blockIdx.x * blockDim.x + threadIdx.x;
    if (i < n4) reinterpret_cast<float4*>(out)[i] = make_float4(0.f, 0.f, 0.f, 0.f);
    if (i == 0) g_acc = 0.f;
}

__global__ void norm_kernel(const float* __restrict__ r, int n) {
    __shared__ float red[NT];
    float s = 0.f;
    for (int i = blockIdx.x * blockDim.x + threadIdx.x; i < n; i += gridDim.x * blockDim.x) {
        float x = r[i];
        s += x * x;
    }
    red[threadIdx.x] = s;
    __syncthreads();
    for (int off = NT / 2; off > 0; off >>= 1) {
        if (threadIdx.x < off) red[threadIdx.x] += red[threadIdx.x + off];
        __syncthreads();
    }
    if (threadIdx.x == 0) atomicAdd(&g_acc, red[0]);
}

// generic transpose: src is R x C row-major; dst[c*R + r] = src[r*C + c]
__global__ void transpose_kernel(const float* __restrict__ src, int R, int C, int which) {
    __shared__ float tile[32][33];
    float* dst = (which == 0) ? g_W1T : (which == 1) ? g_W2T : g_WwT;
    int c0 = blockIdx.x * 32, r0 = blockIdx.y * 32;
    for (int j = threadIdx.y; j < 32; j += 8) {
        int y = r0 + j, x = c0 + threadIdx.x;
        if (y < R && x < C) tile[j][threadIdx.x] = src[y * C + x];
    }
    __syncthreads();
    for (int j = threadIdx.y; j < 32; j += 8) {
        int yc = c0 + j, xr = r0 + threadIdx.x;
        if (yc < C && xr < R) dst[yc * R + xr] = tile[threadIdx.x][j];
    }
}

// ============================================================
// 8x8 GEMM tile with packed f32x2 FMAs.
// Thread owns edges [ty*8, ty*8+8) x feature pairs {tx*2 + j*32} j=0..3.
__device__ __forceinline__ void gemm8x8(const float* __restrict__ sArow,
                                        const float* __restrict__ sW,
                                        int tx, unsigned long long acc[8][4]) {
#pragma unroll 4
    for (int k = 0; k < D; k += 2) {
        unsigned long long b0[4], b1[4];
#pragma unroll
        for (int j = 0; j < 4; j++) {
            b0[j] = *(const unsigned long long*)(sW + k * D + j * 32 + tx * 2);
            b1[j] = *(const unsigned long long*)(sW + (k + 1) * D + j * 32 + tx * 2);
        }
#pragma unroll
        for (int i = 0; i < 8; i++) {
            float2 a = *(const float2*)(sArow + i * 132 + k);
            unsigned long long a0 = dup2(a.x), a1 = dup2(a.y);
#pragma unroll
            for (int j = 0; j < 4; j++) ffma2(acc[i][j], a0, b0[j]);
#pragma unroll
            for (int j = 0; j < 4; j++) ffma2(acc[i][j], a1, b1[j]);
        }
    }
}

__device__ __forceinline__ void zero_acc(unsigned long long acc[8][4]) {
#pragma unroll
    for (int i = 0; i < 8; i++)
#pragma unroll
        for (int j = 0; j < 4; j++) acc[i][j] = 0ull;
}

__device__ __forceinline__ void stage_w2(float* __restrict__ sW, int c, int tid) {
    const float4* src = reinterpret_cast<const float4*>(g_W2T);
    float4* dst = reinterpret_cast<float4*>(sW);
    for (int i = tid; i < D * 32; i += NT) {
        int k = i >> 5, fq = i & 31;
        dst[i] = src[k * 96 + c * 32 + fq];
    }
}

// gate for two edges: wv = bw + fcut(e,:) @ WwT (one chunk's 8 features, packed)
__device__ __forceinline__ void gate_pair(const float* __restrict__ sm, int eA, int eB, int chb,
                                          unsigned long long wvA[4], unsigned long long wvB[4]) {
#pragma unroll
    for (int j = 0; j < 4; j++) {
        unsigned long long bwp = *(const unsigned long long*)(sm + OFF_BW + chb + j * 32);
        wvA[j] = bwp; wvB[j] = bwp;
    }
    const float* fA = sm + OFF_FC + eA * NR;
    const float* fB = sm + OFF_FC + eB * NR;
#pragma unroll
    for (int n = 0; n < NR; n++) {
        unsigned long long a = dup2(fA[n]), b = dup2(fB[n]);
        const float* wwr = sm + OFF_WW + n * 3 * D + chb;
#pragma unroll
        for (int j = 0; j < 4; j++) {
            unsigned long long w2 = *(const unsigned long long*)(wwr + j * 32);
            ffma2(wvA[j], a, w2);
            ffma2(wvB[j], b, w2);
        }
    }
}

// ============================================================
__global__ void __launch_bounds__(NT, 1) fused_kernel(
    const float* __restrict__ s, const float* __restrict__ r, const float* __restrict__ v,
    const float* __restrict__ b1, const float* __restrict__ b2, const float* __restrict__ bw,
    const int* __restrict__ idx_i,
    float* __restrict__ out_v, float* __restrict__ out_s, int E)
{
    extern __shared__ float sm[];
    float* sA  = sm + OFF_A;
    float* sW  = sm + OFF_W;
    int*   sIdx = reinterpret_cast<int*>(sm + OFF_IDX);

    const int tid = threadIdx.x;
    const int e0  = blockIdx.x * ET;
    const int tx  = tid & 15;        // feature pair base tx*2, groups j*32
    const int ty  = tid >> 4;        // edges ty*8 .. ty*8+7
    const int er0 = ty * 8;

    // ---- stage s tile (rows padded to 132 floats) ----
    {
        const float4* src = reinterpret_cast<const float4*>(s) + (size_t)e0 * 32;
        for (int i = tid; i < ET * 32; i += NT) {
            int e = i >> 5, dq = i & 31;
            float4 val = (e0 + e < E) ? src[i] : make_float4(0.f, 0.f, 0.f, 0.f);
            *reinterpret_cast<float4*>(sA + e * 132 + dq * 4) = val;
        }
    }
    // ---- stage W1T ----
    {
        const float4* src = reinterpret_cast<const float4*>(g_W1T);
        float4* dst = reinterpret_cast<float4*>(sW);
        for (int i = tid; i < D * 32; i += NT) dst[i] = src[i];
    }
    // ---- stage WwT ----
    {
        const float4* src = reinterpret_cast<const float4*>(g_WwT);
        float4* dst = reinterpret_cast<float4*>(sm + OFF_WW);
        for (int i = tid; i < NR * 96; i += NT) dst[i] = src[i];
    }
    // ---- biases ----
    for (int i = tid; i < D; i += NT) sm[OFF_B1 + i] = b1[i];
    for (int i = tid; i < 3 * D; i += NT) { sm[OFF_B2 + i] = b2[i]; sm[OFF_BW + i] = bw[i]; }
    // ---- per-edge: idx, org (GLOBAL Frobenius norm!), fcut features ----
    if (tid < ET) {
        int ge = e0 + tid;
        if (ge < E) {
            sIdx[tid] = idx_i[ge];
            float rx = r[ge * 3 + 0], ry = r[ge * 3 + 1], rz = r[ge * 3 + 2];
            float rn = sqrtf(rx * rx + ry * ry + rz * rz);
            float invg = rsqrtf(g_acc);
            sm[OFF_ORG + tid * 3 + 0] = rx * invg;
            sm[OFF_ORG + tid * 3 + 1] = ry * invg;
            sm[OFF_ORG + tid * 3 + 2] = rz * invg;
            float inv_rn = 1.f / rn;
            float base = 0.62831853071795864f * rn;   // pi/RCUT * rn
#pragma unroll
            for (int n = 0; n < NR; n++) {
                float rbf = sinf((float)(n + 1) * base) * inv_rn;
                float fc = (rbf <= 5.0f) ? 0.5f * (cosf(0.62831853071795864f * rbf) + 1.0f) : 0.0f;
                sm[OFF_FC + tid * NR + n] = fc;
            }
        } else {
            sIdx[tid] = 0;
            sm[OFF_ORG + tid * 3 + 0] = 0.f; sm[OFF_ORG + tid * 3 + 1] = 0.f; sm[OFF_ORG + tid * 3 + 2] = 0.f;
#pragma unroll
            for (int n = 0; n < NR; n++) sm[OFF_FC + tid * NR + n] = 0.f;
        }
    }
    __syncthreads();

    unsigned long long acc[8][4];

    // ================= GEMM1: h = silu(S @ W1^T + b1) =================
    zero_acc(acc);
    gemm8x8(sA + er0 * 132, sW, tx, acc);
    __syncthreads();   // all reads of sA / sW done

    {
        float2 bb[4];
#pragma unroll
        for (int j = 0; j < 4; j++) bb[j] = *(const float2*)(sm + OFF_B1 + tx * 2 + j * 32);
#pragma unroll
        for (int i = 0; i < 8; i++) {
#pragma unroll
            for (int j = 0; j < 4; j++) {
                float2 p = unpack2(acc[i][j]);
                float x0 = p.x + bb[j].x, x1 = p.y + bb[j].y;
                float h0 = x0 / (1.f + __expf(-x0));
                float h1 = x1 / (1.f + __expf(-x1));
                *(unsigned long long*)(sA + (er0 + i) * 132 + tx * 2 + j * 32) = pack2(h0, h1);
            }
        }
    }
    stage_w2(sW, 0, tid);
    __syncthreads();

    unsigned long long s0v[8][4];

    // ================= chunk 0: s0 -> registers =================
    zero_acc(acc);
    gemm8x8(sA + er0 * 132, sW, tx, acc);
    __syncthreads();          // sW reads done
    stage_w2(sW, 2, tid);     // next: chunk 2
    {
        const int chb = 0 * D + tx * 2;
        float2 b2p[4];
#pragma unroll
        for (int j = 0; j < 4; j++) b2p[j] = *(const float2*)(sm + OFF_B2 + chb + j * 32);
#pragma unroll
        for (int ii = 0; ii < 8; ii += 2) {
            unsigned long long wvA[4], wvB[4];
            gate_pair(sm, er0 + ii, er0 + ii + 1, chb, wvA, wvB);
#pragma unroll
            for (int j = 0; j < 4; j++) {
                float2 pa = unpack2(acc[ii][j]),     wa = unpack2(wvA[j]);
                float2 pb = unpack2(acc[ii + 1][j]), wb = unpack2(wvB[j]);
                s0v[ii][j]     = pack2(wa.x * (pa.x + b2p[j].x), wa.y * (pa.y + b2p[j].y));
                s0v[ii + 1][j] = pack2(wb.x * (pb.x + b2p[j].x), wb.y * (pb.y + b2p[j].y));
            }
        }
    }
    __syncthreads();

    // ================= chunk 2: s2 + out_v scatter =================
    zero_acc(acc);
    gemm8x8(sA + er0 * 132, sW, tx, acc);
    __syncthreads();
    stage_w2(sW, 1, tid);     // next: chunk 1
    {
        const int chb = 2 * D + tx * 2;
        float2 b2p[4];
#pragma unroll
        for (int j = 0; j < 4; j++) b2p[j] = *(const float2*)(sm + OFF_B2 + chb + j * 32);
#pragma unroll
        for (int ii = 0; ii < 8; ii += 2) {
            unsigned long long wvA[4], wvB[4];
            gate_pair(sm, er0 + ii, er0 + ii + 1, chb, wvA, wvB);
#pragma unroll
            for (int p = 0; p < 2; p++) {
                int i = ii + p;
                int e = er0 + i;
                bool live = (e0 + e) < E;
                int node = sIdx[e];
                float2 s2p[4];
#pragma unroll
                for (int j = 0; j < 4; j++) {
                    float2 pa = unpack2(acc[i][j]);
                    float2 wa = unpack2(p == 0 ? wvA[j] : wvB[j]);
                    s2p[j].x = wa.x * (pa.x + b2p[j].x);
                    s2p[j].y = wa.y * (pa.y + b2p[j].y);
                }
#pragma unroll
                for (int axis = 0; axis < 3; axis++) {
                    float org = sm[OFF_ORG + e * 3 + axis];
                    if (live) {
                        const float* vrow = v + ((size_t)(e0 + e) * 3 + axis) * D + tx * 2;
                        float* dst = out_v + ((size_t)node * 3 + axis) * D + tx * 2;
#pragma unroll
                        for (int j = 0; j < 4; j++) {
                            float2 vl = *(const float2*)(vrow + j * 32);
                            float2 s0p = unpack2(s0v[i][j]);
                            float vx = s2p[j].x * org + s0p.x * vl.x;
                            float vy = s2p[j].y * org + s0p.y * vl.y;
                            red2(dst + j * 32, vx, vy);
                        }
                    }
                }
            }
        }
    }
    __syncthreads();

    // ================= chunk 1: out_s scatter =================
    zero_acc(acc);
    gemm8x8(sA + er0 * 132, sW, tx, acc);
    {
        const int chb = 1 * D + tx * 2;
        float2 b2p[4];
#pragma unroll
        for (int j = 0; j < 4; j++) b2p[j] = *(const float2*)(sm + OFF_B2 + chb + j * 32);
#pragma unroll
        for (int ii = 0; ii < 8; ii += 2) {
            unsigned long long wvA[4], wvB[4];
            gate_pair(sm, er0 + ii, er0 + ii + 1, chb, wvA, wvB);
#pragma unroll
            for (int p = 0; p < 2; p++) {
                int i = ii + p;
                int e = er0 + i;
                bool live = (e0 + e) < E;
                if (!live) continue;
                int node = sIdx[e];
                float* dst = out_s + (size_t)node * D + tx * 2;
#pragma unroll
                for (int j = 0; j < 4; j++) {
                    float2 pa = unpack2(acc[i][j]);
                    float2 wa = unpack2(p == 0 ? wvA[j] : wvB[j]);
                    red2(dst + j * 32,
                         wa.x * (pa.x + b2p[j].x),
                         wa.y * (pa.y + b2p[j].y));
                }
            }
        }
    }
}

// ============================================================
extern "C" void kernel_launch(void* const* d_in, const int* in_sizes, int n_in,
                              void* d_out, int out_size) {
    const float* s   = (const float*)d_in[0];
    const float* r   = (const float*)d_in[1];
    const float* v   = (const float*)d_in[2];
    const float* W1  = (const float*)d_in[3];
    const float* b1  = (const float*)d_in[4];
    const float* W2  = (const float*)d_in[5];
    const float* b2  = (const float*)d_in[6];
    const float* Ww  = (const float*)d_in[7];
    const float* bw  = (const float*)d_in[8];
    const int*   idx = (const int*)d_in[9];
    const int E = in_sizes[9];
    const int N = out_size / (4 * D);            // out = N*3*D (out_v) + N*D (out_s)
    float* out_v = (float*)d_out;
    float* out_s = out_v + (size_t)N * 3 * D;

    cudaFuncSetAttribute(fused_kernel, cudaFuncAttributeMaxDynamicSharedMemorySize, (int)SMEM_BYTES);

    int n4 = out_size / 4;
    zero_kernel<<<(n4 + NT - 1) / NT, NT>>>((float*)d_out, n4);
    norm_kernel<<<256, NT>>>(r, E * 3);

    dim3 tb(32, 8);
    transpose_kernel<<<dim3(4, 4),  tb>>>(W1, D, D, 0);          // -> g_W1T [k][f]
    transpose_kernel<<<dim3(4, 12), tb>>>(W2, 3 * D, D, 1);      // -> g_W2T [k][ch]
    transpose_kernel<<<dim3(1, 12), tb>>>(Ww, 3 * D, NR, 2);     // -> g_WwT [n][ch]

    int grid = (E + ET - 1) / ET;
    fused_kernel<<<grid, NT, SMEM_BYTES>>>(s, r, v, b1, b2, bw, idx, out_v, out_s, E);
}